// round 14
// baseline (speedup 1.0000x reference)
#include <cuda_runtime.h>
#include <math.h>
#include <stdint.h>

#define HDIM 256
#define NHEADS 8
#define DH 32
#define NMAX 4096

// ---------------- scratch (static __device__ arrays: no allocations) -------
__device__ __align__(16) float g_Q   [NMAX * HDIM];
__device__ __align__(16) float g_K   [NMAX * HDIM];
__device__ __align__(16) float g_V   [NMAX * HDIM];
__device__ __align__(16) float g_attH[NMAX * HDIM];
__device__ __align__(16) float g_att [NMAX * HDIM];
__device__ __align__(16) float g_Atop[NMAX * HDIM];
__device__ __align__(16) float g_Abot[NMAX * HDIM];
__device__ __align__(16) float g_Hsum[NMAX * HDIM];
__device__ __align__(16) float g_msg [NMAX * HDIM];
__device__ __align__(16) float g_T1  [NMAX * HDIM];
__device__ __align__(16) float g_deg [NMAX];

// ---------------- tf32 helpers ---------------------------------------------
__device__ __forceinline__ uint32_t f2tf(float x) {
    uint32_t r;
    asm("cvt.rna.tf32.f32 %0, %1;" : "=r"(r) : "f"(x));
    return r;
}
__device__ __forceinline__ void tfsplit(float x, uint32_t& hi, uint32_t& lo) {
    hi = f2tf(x);
    lo = f2tf(x - __uint_as_float(hi));
}
__device__ __forceinline__ void mma_tf32(float d[4], const uint32_t a[4],
                                         uint32_t b0, uint32_t b1) {
    asm volatile(
        "mma.sync.aligned.m16n8k8.row.col.f32.tf32.tf32.f32 "
        "{%0,%1,%2,%3}, {%4,%5,%6,%7}, {%8,%9}, {%0,%1,%2,%3};"
        : "+f"(d[0]), "+f"(d[1]), "+f"(d[2]), "+f"(d[3])
        : "r"(a[0]), "r"(a[1]), "r"(a[2]), "r"(a[3]), "r"(b0), "r"(b1));
}
__device__ __forceinline__ void cpa16(void* smem, const void* g) {
    uint32_t s = (uint32_t)__cvta_generic_to_shared(smem);
    asm volatile("cp.async.cg.shared.global [%0], [%1], 16;"
                 :: "r"(s), "l"(g) : "memory");
}

struct Jobs3 {
    const float* W[3];
    const float* bias[3];
    float*       C[3];
};

// ---------------- tensor-core GEMM body (3xTF32) ----------------------------
#define AS_STR 36
#define WS_STR 72

template<bool RELU, bool ADD, bool DEGB>
__device__ __forceinline__ void gemm_body(
    const float* __restrict__ A, const float* __restrict__ W,
    const float* bias, const float* __restrict__ Dadd,
    const float* __restrict__ deg, float* __restrict__ C,
    int M, int K, int N,
    uint32_t* Ahi, uint32_t* Alo, uint32_t* Whi, uint32_t* Wlo)
{
    const int t    = threadIdx.x;
    const int w    = t >> 5;
    const int lane = t & 31;
    const int g    = lane >> 2;
    const int tq   = lane & 3;
    const int wm   = (w >> 2) * 32;
    const int wn   = (w & 3) * 16;
    const int bm   = blockIdx.y * 64;
    const int bn   = blockIdx.x * 64;

    float acc[2][2][4];
    #pragma unroll
    for (int mh = 0; mh < 2; mh++)
        #pragma unroll
        for (int nb = 0; nb < 2; nb++)
            #pragma unroll
            for (int j = 0; j < 4; j++) acc[mh][nb][j] = 0.f;

    const int arow = t >> 2, akb = (t & 3) * 8;
    const int wkk  = t >> 3, wnb = (t & 7) * 8;

    for (int k0 = 0; k0 < K; k0 += 32) {
        __syncthreads();
        {
            const float* src = &A[(size_t)(bm + arow) * K + k0 + akb];
            #pragma unroll
            for (int j = 0; j < 8; j += 4) {
                float4 v = *(const float4*)(src + j);
                uint32_t h0,l0,h1,l1,h2,l2,h3,l3;
                tfsplit(v.x,h0,l0); tfsplit(v.y,h1,l1);
                tfsplit(v.z,h2,l2); tfsplit(v.w,h3,l3);
                *(uint4*)&Ahi[arow * AS_STR + akb + j] = make_uint4(h0,h1,h2,h3);
                *(uint4*)&Alo[arow * AS_STR + akb + j] = make_uint4(l0,l1,l2,l3);
            }
        }
        {
            const float* src = &W[(size_t)(k0 + wkk) * N + bn + wnb];
            #pragma unroll
            for (int j = 0; j < 8; j += 4) {
                float4 v = *(const float4*)(src + j);
                uint32_t h0,l0,h1,l1,h2,l2,h3,l3;
                tfsplit(v.x,h0,l0); tfsplit(v.y,h1,l1);
                tfsplit(v.z,h2,l2); tfsplit(v.w,h3,l3);
                *(uint4*)&Whi[wkk * WS_STR + wnb + j] = make_uint4(h0,h1,h2,h3);
                *(uint4*)&Wlo[wkk * WS_STR + wnb + j] = make_uint4(l0,l1,l2,l3);
            }
        }
        __syncthreads();

        #pragma unroll
        for (int kc = 0; kc < 4; kc++) {
            uint32_t bh[2][2], bl[2][2];
            #pragma unroll
            for (int nb = 0; nb < 2; nb++) {
                int i0 = (kc * 8 + tq) * WS_STR + wn + nb * 8 + g;
                int i1 = i0 + 4 * WS_STR;
                bh[nb][0] = Whi[i0]; bh[nb][1] = Whi[i1];
                bl[nb][0] = Wlo[i0]; bl[nb][1] = Wlo[i1];
            }
            #pragma unroll
            for (int mh = 0; mh < 2; mh++) {
                int r0 = (wm + mh * 16 + g) * AS_STR + kc * 8 + tq;
                int r1 = r0 + 8 * AS_STR;
                uint32_t ah[4] = {Ahi[r0], Ahi[r1], Ahi[r0 + 4], Ahi[r1 + 4]};
                uint32_t al[4] = {Alo[r0], Alo[r1], Alo[r0 + 4], Alo[r1 + 4]};
                #pragma unroll
                for (int nb = 0; nb < 2; nb++) {
                    mma_tf32(acc[mh][nb], ah, bh[nb][0], bh[nb][1]);
                    mma_tf32(acc[mh][nb], al, bh[nb][0], bh[nb][1]);
                    mma_tf32(acc[mh][nb], ah, bl[nb][0], bl[nb][1]);
                }
            }
        }
    }

    #pragma unroll
    for (int mh = 0; mh < 2; mh++) {
        int row0 = bm + wm + mh * 16 + g;
        int row1 = row0 + 8;
        float d0 = DEGB ? deg[row0] : 1.f;
        float d1 = DEGB ? deg[row1] : 1.f;
        #pragma unroll
        for (int nb = 0; nb < 2; nb++) {
            int col = bn + wn + nb * 8 + tq * 2;
            float v0 = acc[mh][nb][0], v1 = acc[mh][nb][1];
            float v2 = acc[mh][nb][2], v3 = acc[mh][nb][3];
            if (ADD) {
                float2 x0 = *(const float2*)&Dadd[(size_t)row0 * N + col];
                float2 x1 = *(const float2*)&Dadd[(size_t)row1 * N + col];
                v0 += x0.x; v1 += x0.y; v2 += x1.x; v3 += x1.y;
            }
            if (bias) {
                float b0 = bias[col], b1 = bias[col + 1];
                if (DEGB) { v0 += d0 * b0; v1 += d0 * b1; v2 += d1 * b0; v3 += d1 * b1; }
                else      { v0 += b0;      v1 += b1;      v2 += b0;      v3 += b1; }
            }
            if (RELU) {
                v0 = fmaxf(v0, 0.f); v1 = fmaxf(v1, 0.f);
                v2 = fmaxf(v2, 0.f); v3 = fmaxf(v3, 0.f);
            }
            *(float2*)&C[(size_t)row0 * N + col] = make_float2(v0, v1);
            *(float2*)&C[(size_t)row1 * N + col] = make_float2(v2, v3);
        }
    }
}

template<bool RELU, bool ADD, bool DEGB>
__global__ void __launch_bounds__(256) gemm_mma(
    const float* __restrict__ A, const float* __restrict__ W,
    const float* bias, const float* __restrict__ Dadd,
    const float* __restrict__ deg, float* __restrict__ C,
    int M, int K, int N)
{
    __shared__ uint32_t Ahi[64 * AS_STR];
    __shared__ uint32_t Alo[64 * AS_STR];
    __shared__ uint32_t Whi[32 * WS_STR];
    __shared__ uint32_t Wlo[32 * WS_STR];
    gemm_body<RELU, ADD, DEGB>(A, W, bias, Dadd, deg, C, M, K, N,
                               Ahi, Alo, Whi, Wlo);
}

// batched variant: blockIdx.z selects (W, bias, C); same A for all three.
__global__ void __launch_bounds__(256) gemm_mma3(
    const float* __restrict__ A, Jobs3 jobs, int M, int K, int N)
{
    __shared__ uint32_t Ahi[64 * AS_STR];
    __shared__ uint32_t Alo[64 * AS_STR];
    __shared__ uint32_t Whi[32 * WS_STR];
    __shared__ uint32_t Wlo[32 * WS_STR];
    const int z = blockIdx.z;
    gemm_body<false, false, false>(A, jobs.W[z], jobs.bias[z], nullptr, nullptr,
                                   jobs.C[z], M, K, N, Ahi, Alo, Whi, Wlo);
}

// ---------------- flash attention: cp.async double-buffer + 2xTF32 ----------
// K/V land raw via cp.async, then each thread rna-rounds the exact words it
// copied (own cp.async data is visible to the issuing thread after
// wait_group; the existing publish __syncthreads covers other threads).
// Q/P stay rna hi/lo split in registers (2 mmas per logical mma).
#define KS_STR 36
#define VS_STR 40

__global__ void __launch_bounds__(256) flash_mma(
    const float* __restrict__ Qm, const float* __restrict__ Km,
    const float* __restrict__ Vm, float* __restrict__ O, int N)
{
    __shared__ uint32_t Khi[2][64 * KS_STR];
    __shared__ uint32_t Vhi[2][64 * VS_STR];

    const int t    = threadIdx.x;
    const int w    = t >> 5;
    const int lane = t & 31;
    const int g    = lane >> 2;
    const int tq   = lane & 3;
    const int h    = blockIdx.y;
    const int q0   = blockIdx.x * 128;
    const float sc = 1.44269504088896f / sqrtf((float)DH);

    // ---- stage Q tile (128 x 32) raw into buffer-0 regions ----
    for (int i = t; i < 128 * 8; i += 256) {
        int row = i >> 3, c = (i & 7) << 2;
        float4 qv = *(const float4*)&Qm[(size_t)(q0 + row) * HDIM + h * DH + c];
        uint32_t* dst = (row < 64) ? &Khi[0][row * KS_STR + c]
                                   : &Vhi[0][(row - 64) * VS_STR + c];
        *(float4*)dst = qv;
    }
    __syncthreads();

    // ---- Q fragments (rna hi/lo), scaled; registers for whole kernel ----
    uint32_t qhi[4][4], qlo[4][4];
    {
        int r0 = w * 16 + g;
        int r1 = r0 + 8;
        const float* p0 = (const float*)((r0 < 64) ? &Khi[0][r0 * KS_STR]
                                                   : &Vhi[0][(r0 - 64) * VS_STR]);
        const float* p1 = (const float*)((r1 < 64) ? &Khi[0][r1 * KS_STR]
                                                   : &Vhi[0][(r1 - 64) * VS_STR]);
        #pragma unroll
        for (int kc = 0; kc < 4; kc++) {
            int c0 = kc * 8 + tq, c1 = c0 + 4;
            tfsplit(p0[c0] * sc, qhi[kc][0], qlo[kc][0]);
            tfsplit(p1[c0] * sc, qhi[kc][1], qlo[kc][1]);
            tfsplit(p0[c1] * sc, qhi[kc][2], qlo[kc][2]);
            tfsplit(p1[c1] * sc, qhi[kc][3], qlo[kc][3]);
        }
    }
    __syncthreads();   // all warps done reading Q staging before tile-0 load

    // ---- prefetch tile 0 into buffer 0 (raw fp32, pure copy) ----
    for (int i = t; i < 64 * 8; i += 256) {
        int n = i >> 3, c = (i & 7) << 2;
        size_t gidx = (size_t)n * HDIM + h * DH + c;
        cpa16(&Khi[0][n * KS_STR + c], &Km[gidx]);
        cpa16(&Vhi[0][n * VS_STR + c], &Vm[gidx]);
    }
    asm volatile("cp.async.commit_group;" ::: "memory");

    float oacc[4][4];
    #pragma unroll
    for (int i = 0; i < 4; i++)
        #pragma unroll
        for (int j = 0; j < 4; j++) oacc[i][j] = 0.f;
    float mi[2] = {-1e30f, -1e30f};
    float li[2] = {0.f, 0.f};

    const int ntiles = N >> 6;
    for (int it = 0; it < ntiles; it++) {
        const int p = it & 1;

        // prefetch next tile into the other buffer
        if (it + 1 < ntiles) {
            int kb1 = (it + 1) << 6;
            for (int i = t; i < 64 * 8; i += 256) {
                int n = i >> 3, c = (i & 7) << 2;
                size_t gidx = (size_t)(kb1 + n) * HDIM + h * DH + c;
                cpa16(&Khi[1 - p][n * KS_STR + c], &Km[gidx]);
                cpa16(&Vhi[1 - p][n * VS_STR + c], &Vm[gidx]);
            }
            asm volatile("cp.async.commit_group;" ::: "memory");
            asm volatile("cp.async.wait_group 1;" ::: "memory");
        } else {
            asm volatile("cp.async.wait_group 0;" ::: "memory");
        }

        // rna-round this thread's own copied words in place (same index
        // partition as the issuing loop -> own-data visibility, no barrier)
        for (int i = t; i < 64 * 8; i += 256) {
            int n = i >> 3, c = (i & 7) << 2;
            uint4* kp = (uint4*)&Khi[p][n * KS_STR + c];
            uint4 kw = *kp;
            kw.x = f2tf(__uint_as_float(kw.x));
            kw.y = f2tf(__uint_as_float(kw.y));
            kw.z = f2tf(__uint_as_float(kw.z));
            kw.w = f2tf(__uint_as_float(kw.w));
            *kp = kw;
            uint4* vp = (uint4*)&Vhi[p][n * VS_STR + c];
            uint4 vw = *vp;
            vw.x = f2tf(__uint_as_float(vw.x));
            vw.y = f2tf(__uint_as_float(vw.y));
            vw.z = f2tf(__uint_as_float(vw.z));
            vw.w = f2tf(__uint_as_float(vw.w));
            *vp = vw;
        }
        __syncthreads();   // tile `it` (rounded) visible to all warps

        // ---- S = Q @ K^T : 2xTF32 ----
        float sb[8][4];
        #pragma unroll
        for (int nb = 0; nb < 8; nb++)
            #pragma unroll
            for (int j = 0; j < 4; j++) sb[nb][j] = 0.f;

        #pragma unroll
        for (int kc = 0; kc < 4; kc++) {
            #pragma unroll
            for (int nb = 0; nb < 8; nb++) {
                int base = (nb * 8 + g) * KS_STR + kc * 8 + tq;
                uint32_t b0h = Khi[p][base], b1h = Khi[p][base + 4];
                mma_tf32(sb[nb], qhi[kc], b0h, b1h);
                mma_tf32(sb[nb], qlo[kc], b0h, b1h);
            }
        }

        // ---- online softmax on C fragments ----
        #pragma unroll
        for (int hf = 0; hf < 2; hf++) {
            int e0 = hf * 2, e1 = hf * 2 + 1;
            float rm = -1e30f;
            #pragma unroll
            for (int nb = 0; nb < 8; nb++)
                rm = fmaxf(rm, fmaxf(sb[nb][e0], sb[nb][e1]));
            rm = fmaxf(rm, __shfl_xor_sync(0xffffffffu, rm, 1));
            rm = fmaxf(rm, __shfl_xor_sync(0xffffffffu, rm, 2));
            float mn = fmaxf(mi[hf], rm);
            float c  = exp2f(mi[hf] - mn);
            float rs = 0.f;
            #pragma unroll
            for (int nb = 0; nb < 8; nb++) {
                sb[nb][e0] = exp2f(sb[nb][e0] - mn);
                sb[nb][e1] = exp2f(sb[nb][e1] - mn);
                rs += sb[nb][e0] + sb[nb][e1];
            }
            rs += __shfl_xor_sync(0xffffffffu, rs, 1);
            rs += __shfl_xor_sync(0xffffffffu, rs, 2);
            li[hf] = li[hf] * c + rs;
            mi[hf] = mn;
            #pragma unroll
            for (int nbo = 0; nbo < 4; nbo++) {
                oacc[nbo][e0] *= c;
                oacc[nbo][e1] *= c;
            }
        }

        // ---- O += P @ V : P rna hi/lo in regs, V rna tf32 (2xTF32) ----
        const int srcA = (lane & ~3) + (tq >> 1);
        const int srcB = srcA + 2;
        const bool odd = (tq & 1);
        #pragma unroll
        for (int kc = 0; kc < 8; kc++) {
            float vA0 = __shfl_sync(0xffffffffu, sb[kc][0], srcA);
            float vA1 = __shfl_sync(0xffffffffu, sb[kc][1], srcA);
            float vA2 = __shfl_sync(0xffffffffu, sb[kc][2], srcA);
            float vA3 = __shfl_sync(0xffffffffu, sb[kc][3], srcA);
            float vB0 = __shfl_sync(0xffffffffu, sb[kc][0], srcB);
            float vB1 = __shfl_sync(0xffffffffu, sb[kc][1], srcB);
            float vB2 = __shfl_sync(0xffffffffu, sb[kc][2], srcB);
            float vB3 = __shfl_sync(0xffffffffu, sb[kc][3], srcB);
            float pa0 = odd ? vA1 : vA0;
            float pa1 = odd ? vA3 : vA2;
            float pa2 = odd ? vB1 : vB0;
            float pa3 = odd ? vB3 : vB2;
            uint32_t phi[4], plo[4];
            tfsplit(pa0, phi[0], plo[0]);
            tfsplit(pa1, phi[1], plo[1]);
            tfsplit(pa2, phi[2], plo[2]);
            tfsplit(pa3, phi[3], plo[3]);
            int b0 = (kc * 8 + tq) * VS_STR + g;
            int b1 = (kc * 8 + tq + 4) * VS_STR + g;
            #pragma unroll
            for (int nbo = 0; nbo < 4; nbo++) {
                uint32_t v0h = Vhi[p][b0 + nbo * 8], v1h = Vhi[p][b1 + nbo * 8];
                mma_tf32(oacc[nbo], phi, v0h, v1h);
                mma_tf32(oacc[nbo], plo, v0h, v1h);
            }
        }
        __syncthreads();   // tile `it` fully consumed; next prefetch may write
    }

    float inv0 = 1.f / li[0];
    float inv1 = 1.f / li[1];
    int r0 = q0 + w * 16 + g;
    #pragma unroll
    for (int nbo = 0; nbo < 4; nbo++) {
        int col = h * DH + nbo * 8 + tq * 2;
        *(float2*)&O[(size_t)r0 * HDIM + col] =
            make_float2(oacc[nbo][0] * inv0, oacc[nbo][1] * inv0);
        *(float2*)&O[(size_t)(r0 + 8) * HDIM + col] =
            make_float2(oacc[nbo][2] * inv1, oacc[nbo][3] * inv1);
    }
}

// ---------------- edge kernel: Hsum[dst] += relu(Atop[src] + Abot[dst]) ----
__global__ void edge_k(const float* __restrict__ At, const float* __restrict__ Ab,
                       const int* __restrict__ edges, float* __restrict__ Hsum,
                       float* __restrict__ deg, int E)
{
    const int lane   = threadIdx.x & 31;
    const int gw     = (blockIdx.x * blockDim.x + threadIdx.x) >> 5;
    const int nwarps = (gridDim.x * blockDim.x) >> 5;

    for (int e = gw; e < E; e += nwarps) {
        int src = edges[2 * e + 0];
        int dst = edges[2 * e + 1];
        const float4* ps = (const float4*)(At + (size_t)src * HDIM);
        const float4* pd = (const float4*)(Ab + (size_t)dst * HDIM);
        float* po = Hsum + (size_t)dst * HDIM;
        #pragma unroll
        for (int i = 0; i < 2; i++) {
            int idx = lane + 32 * i;
            float4 a = ps[idx], b = pd[idx];
            float4 r;
            r.x = fmaxf(a.x + b.x, 0.f);
            r.y = fmaxf(a.y + b.y, 0.f);
            r.z = fmaxf(a.z + b.z, 0.f);
            r.w = fmaxf(a.w + b.w, 0.f);
            asm volatile("red.global.add.v4.f32 [%0], {%1, %2, %3, %4};"
                         :: "l"(po + idx * 4), "f"(r.x), "f"(r.y), "f"(r.z), "f"(r.w)
                         : "memory");
        }
        if (lane == 0) atomicAdd(deg + dst, 1.f);
    }
}

// ---------------- launch ---------------------------------------------------
extern "C" void kernel_launch(void* const* d_in, const int* in_sizes, int n_in,
                              void* d_out, int out_size)
{
    const float* x    = (const float*)d_in[0];
    const int*   edges= (const int*)  d_in[1];
    const float* Wq   = (const float*)d_in[2];
    const float* Wk   = (const float*)d_in[3];
    const float* Wv   = (const float*)d_in[4];
    const float* bq   = (const float*)d_in[5];
    const float* bk   = (const float*)d_in[6];
    const float* bv   = (const float*)d_in[7];
    const float* Wo   = (const float*)d_in[8];
    const float* bo   = (const float*)d_in[9];
    const float* Wm1  = (const float*)d_in[10];
    const float* bm1  = (const float*)d_in[11];
    const float* Wm2  = (const float*)d_in[12];
    const float* bm2  = (const float*)d_in[13];
    const float* Wu1  = (const float*)d_in[14];
    const float* bu1  = (const float*)d_in[15];
    const float* Wu2  = (const float*)d_in[16];
    const float* bu2  = (const float*)d_in[17];
    float* out = (float*)d_out;

    const int N = in_sizes[0] / HDIM;   // 4096
    const int E = in_sizes[1] / 2;      // 131072

    float *Q, *K, *V, *attH, *att, *Atop, *Abot, *Hsum, *msg, *T1, *deg;
    cudaGetSymbolAddress((void**)&Q,    g_Q);
    cudaGetSymbolAddress((void**)&K,    g_K);
    cudaGetSymbolAddress((void**)&V,    g_V);
    cudaGetSymbolAddress((void**)&attH, g_attH);
    cudaGetSymbolAddress((void**)&att,  g_att);
    cudaGetSymbolAddress((void**)&Atop, g_Atop);
    cudaGetSymbolAddress((void**)&Abot, g_Abot);
    cudaGetSymbolAddress((void**)&Hsum, g_Hsum);
    cudaGetSymbolAddress((void**)&msg,  g_msg);
    cudaGetSymbolAddress((void**)&T1,   g_T1);
    cudaGetSymbolAddress((void**)&deg,  g_deg);

    dim3 gB(256);
    dim3 gG (HDIM / 64, N / 64);        // (4, 64)  = 256 blocks
    dim3 gG3(HDIM / 64, N / 64, 3);     // (4, 64, 3) = 768 blocks

    cudaMemsetAsync(Hsum, 0, (size_t)N * HDIM * sizeof(float));
    cudaMemsetAsync(deg,  0, (size_t)N * sizeof(float));

    // QKV projections (batched: blockIdx.z selects q/k/v)
    Jobs3 jq;
    jq.W[0] = Wq; jq.W[1] = Wk; jq.W[2] = Wv;
    jq.bias[0] = bq; jq.bias[1] = bk; jq.bias[2] = bv;
    jq.C[0] = Q; jq.C[1] = K; jq.C[2] = V;
    gemm_mma3<<<gG3, gB>>>(x, jq, N, HDIM, HDIM);

    // attention (tensor cores, cp.async double-buffered 2xTF32, rna K/V)
    flash_mma<<<dim3(N / 128, NHEADS), 256>>>(Q, K, V, attH, N);

    // output projection
    gemm_mma<false, false, false><<<gG, gB>>>(attH, Wo, bo, nullptr, nullptr, att, N, HDIM, HDIM);

    // batched: Atop = att@Wm1[:256]+bm1 ; Abot = att@Wm1[256:] ; T1 = att@Wu1[:256]+bu1
    Jobs3 ja;
    ja.W[0] = Wm1; ja.W[1] = Wm1 + HDIM * HDIM; ja.W[2] = Wu1;
    ja.bias[0] = bm1; ja.bias[1] = nullptr; ja.bias[2] = bu1;
    ja.C[0] = Atop; ja.C[1] = Abot; ja.C[2] = T1;
    gemm_mma3<<<gG3, gB>>>(att, ja, N, HDIM, HDIM);

    // per-edge relu + segment-sum of hidden
    edge_k<<<512, 256>>>(Atop, Abot, edges, Hsum, deg, E);

    // messages = Hsum @ Wm2 + deg * bm2
    gemm_mma<false, false, true><<<gG, gB>>>(Hsum, Wm2, bm2, nullptr, deg, msg, N, HDIM, HDIM);

    // T1 = relu(msg @ Wu1[256:] + T1)
    gemm_mma<true, true, false><<<gG, gB>>>(msg, Wu1 + HDIM * HDIM, nullptr, T1, nullptr, T1, N, HDIM, HDIM);

    // output
    gemm_mma<false, false, false><<<gG, gB>>>(T1, Wu2, bu2, nullptr, nullptr, out, N, HDIM, HDIM);
}

// round 15
// speedup vs baseline: 1.1323x; 1.1323x over previous
#include <cuda_runtime.h>
#include <math.h>
#include <stdint.h>

#define HDIM 256
#define NHEADS 8
#define DH 32
#define NMAX 4096

// ---------------- scratch (static __device__ arrays: no allocations) -------
__device__ __align__(16) float g_Q   [NMAX * HDIM];
__device__ __align__(16) float g_K   [NMAX * HDIM];
__device__ __align__(16) float g_V   [NMAX * HDIM];
__device__ __align__(16) float g_attH[NMAX * HDIM];
__device__ __align__(16) float g_att [NMAX * HDIM];
__device__ __align__(16) float g_Atop[NMAX * HDIM];
__device__ __align__(16) float g_Abot[NMAX * HDIM];
__device__ __align__(16) float g_Hsum[NMAX * HDIM];
__device__ __align__(16) float g_msg [NMAX * HDIM];
__device__ __align__(16) float g_T1  [NMAX * HDIM];
__device__ __align__(16) float g_deg [NMAX];

// ---------------- tf32 helpers ---------------------------------------------
__device__ __forceinline__ uint32_t f2tf(float x) {
    uint32_t r;
    asm("cvt.rna.tf32.f32 %0, %1;" : "=r"(r) : "f"(x));
    return r;
}
__device__ __forceinline__ void tfsplit(float x, uint32_t& hi, uint32_t& lo) {
    hi = f2tf(x);
    lo = f2tf(x - __uint_as_float(hi));
}
__device__ __forceinline__ void mma_tf32(float d[4], const uint32_t a[4],
                                         uint32_t b0, uint32_t b1) {
    asm volatile(
        "mma.sync.aligned.m16n8k8.row.col.f32.tf32.tf32.f32 "
        "{%0,%1,%2,%3}, {%4,%5,%6,%7}, {%8,%9}, {%0,%1,%2,%3};"
        : "+f"(d[0]), "+f"(d[1]), "+f"(d[2]), "+f"(d[3])
        : "r"(a[0]), "r"(a[1]), "r"(a[2]), "r"(a[3]), "r"(b0), "r"(b1));
}
__device__ __forceinline__ void cpa16(void* smem, const void* g) {
    uint32_t s = (uint32_t)__cvta_generic_to_shared(smem);
    asm volatile("cp.async.cg.shared.global [%0], [%1], 16;"
                 :: "r"(s), "l"(g) : "memory");
}

struct Jobs3 {
    const float* W[3];
    const float* bias[3];
    float*       C[3];
};

// ---------------- tensor-core GEMM body (3xTF32) ----------------------------
#define AS_STR 36
#define WS_STR 72

template<bool RELU, bool ADD, bool DEGB>
__device__ __forceinline__ void gemm_body(
    const float* __restrict__ A, const float* __restrict__ W,
    const float* bias, const float* __restrict__ Dadd,
    const float* __restrict__ deg, float* __restrict__ C,
    int M, int K, int N,
    uint32_t* Ahi, uint32_t* Alo, uint32_t* Whi, uint32_t* Wlo)
{
    const int t    = threadIdx.x;
    const int w    = t >> 5;
    const int lane = t & 31;
    const int g    = lane >> 2;
    const int tq   = lane & 3;
    const int wm   = (w >> 2) * 32;
    const int wn   = (w & 3) * 16;
    const int bm   = blockIdx.y * 64;
    const int bn   = blockIdx.x * 64;

    float acc[2][2][4];
    #pragma unroll
    for (int mh = 0; mh < 2; mh++)
        #pragma unroll
        for (int nb = 0; nb < 2; nb++)
            #pragma unroll
            for (int j = 0; j < 4; j++) acc[mh][nb][j] = 0.f;

    const int arow = t >> 2, akb = (t & 3) * 8;
    const int wkk  = t >> 3, wnb = (t & 7) * 8;

    for (int k0 = 0; k0 < K; k0 += 32) {
        __syncthreads();
        {
            const float* src = &A[(size_t)(bm + arow) * K + k0 + akb];
            #pragma unroll
            for (int j = 0; j < 8; j += 4) {
                float4 v = *(const float4*)(src + j);
                uint32_t h0,l0,h1,l1,h2,l2,h3,l3;
                tfsplit(v.x,h0,l0); tfsplit(v.y,h1,l1);
                tfsplit(v.z,h2,l2); tfsplit(v.w,h3,l3);
                *(uint4*)&Ahi[arow * AS_STR + akb + j] = make_uint4(h0,h1,h2,h3);
                *(uint4*)&Alo[arow * AS_STR + akb + j] = make_uint4(l0,l1,l2,l3);
            }
        }
        {
            const float* src = &W[(size_t)(k0 + wkk) * N + bn + wnb];
            #pragma unroll
            for (int j = 0; j < 8; j += 4) {
                float4 v = *(const float4*)(src + j);
                uint32_t h0,l0,h1,l1,h2,l2,h3,l3;
                tfsplit(v.x,h0,l0); tfsplit(v.y,h1,l1);
                tfsplit(v.z,h2,l2); tfsplit(v.w,h3,l3);
                *(uint4*)&Whi[wkk * WS_STR + wnb + j] = make_uint4(h0,h1,h2,h3);
                *(uint4*)&Wlo[wkk * WS_STR + wnb + j] = make_uint4(l0,l1,l2,l3);
            }
        }
        __syncthreads();

        #pragma unroll
        for (int kc = 0; kc < 4; kc++) {
            uint32_t bh[2][2], bl[2][2];
            #pragma unroll
            for (int nb = 0; nb < 2; nb++) {
                int i0 = (kc * 8 + tq) * WS_STR + wn + nb * 8 + g;
                int i1 = i0 + 4 * WS_STR;
                bh[nb][0] = Whi[i0]; bh[nb][1] = Whi[i1];
                bl[nb][0] = Wlo[i0]; bl[nb][1] = Wlo[i1];
            }
            #pragma unroll
            for (int mh = 0; mh < 2; mh++) {
                int r0 = (wm + mh * 16 + g) * AS_STR + kc * 8 + tq;
                int r1 = r0 + 8 * AS_STR;
                uint32_t ah[4] = {Ahi[r0], Ahi[r1], Ahi[r0 + 4], Ahi[r1 + 4]};
                uint32_t al[4] = {Alo[r0], Alo[r1], Alo[r0 + 4], Alo[r1 + 4]};
                #pragma unroll
                for (int nb = 0; nb < 2; nb++) {
                    mma_tf32(acc[mh][nb], ah, bh[nb][0], bh[nb][1]);
                    mma_tf32(acc[mh][nb], al, bh[nb][0], bh[nb][1]);
                    mma_tf32(acc[mh][nb], ah, bl[nb][0], bl[nb][1]);
                }
            }
        }
    }

    #pragma unroll
    for (int mh = 0; mh < 2; mh++) {
        int row0 = bm + wm + mh * 16 + g;
        int row1 = row0 + 8;
        float d0 = DEGB ? deg[row0] : 1.f;
        float d1 = DEGB ? deg[row1] : 1.f;
        #pragma unroll
        for (int nb = 0; nb < 2; nb++) {
            int col = bn + wn + nb * 8 + tq * 2;
            float v0 = acc[mh][nb][0], v1 = acc[mh][nb][1];
            float v2 = acc[mh][nb][2], v3 = acc[mh][nb][3];
            if (ADD) {
                float2 x0 = *(const float2*)&Dadd[(size_t)row0 * N + col];
                float2 x1 = *(const float2*)&Dadd[(size_t)row1 * N + col];
                v0 += x0.x; v1 += x0.y; v2 += x1.x; v3 += x1.y;
            }
            if (bias) {
                float b0 = bias[col], b1 = bias[col + 1];
                if (DEGB) { v0 += d0 * b0; v1 += d0 * b1; v2 += d1 * b0; v3 += d1 * b1; }
                else      { v0 += b0;      v1 += b1;      v2 += b0;      v3 += b1; }
            }
            if (RELU) {
                v0 = fmaxf(v0, 0.f); v1 = fmaxf(v1, 0.f);
                v2 = fmaxf(v2, 0.f); v3 = fmaxf(v3, 0.f);
            }
            *(float2*)&C[(size_t)row0 * N + col] = make_float2(v0, v1);
            *(float2*)&C[(size_t)row1 * N + col] = make_float2(v2, v3);
        }
    }
}

template<bool RELU, bool ADD, bool DEGB>
__global__ void __launch_bounds__(256) gemm_mma(
    const float* __restrict__ A, const float* __restrict__ W,
    const float* bias, const float* __restrict__ Dadd,
    const float* __restrict__ deg, float* __restrict__ C,
    int M, int K, int N)
{
    __shared__ uint32_t Ahi[64 * AS_STR];
    __shared__ uint32_t Alo[64 * AS_STR];
    __shared__ uint32_t Whi[32 * WS_STR];
    __shared__ uint32_t Wlo[32 * WS_STR];
    gemm_body<RELU, ADD, DEGB>(A, W, bias, Dadd, deg, C, M, K, N,
                               Ahi, Alo, Whi, Wlo);
}

// batched variant: blockIdx.z selects (W, bias, C); same A for all three.
__global__ void __launch_bounds__(256) gemm_mma3(
    const float* __restrict__ A, Jobs3 jobs, int M, int K, int N)
{
    __shared__ uint32_t Ahi[64 * AS_STR];
    __shared__ uint32_t Alo[64 * AS_STR];
    __shared__ uint32_t Whi[32 * WS_STR];
    __shared__ uint32_t Wlo[32 * WS_STR];
    const int z = blockIdx.z;
    gemm_body<false, false, false>(A, jobs.W[z], jobs.bias[z], nullptr, nullptr,
                                   jobs.C[z], M, K, N, Ahi, Alo, Whi, Wlo);
}

// ---------------- flash attention: cp.async double-buffer, asymmetric tf32 --
// S = Q@K^T uses Q hi/lo (2 mmas); O += P@V uses P as a SINGLE rna tf32
// (1 mma) — P is a softmax weight in (0,1], so the dropped lo term is an
// unbiased ~2.4e-4 per-element wiggle that averages out over the 4096-key
// softmax. K/V rna-rounded in smem after cp.async (round-14 scheme).
#define KS_STR 36
#define VS_STR 40

__global__ void __launch_bounds__(256) flash_mma(
    const float* __restrict__ Qm, const float* __restrict__ Km,
    const float* __restrict__ Vm, float* __restrict__ O, int N)
{
    __shared__ uint32_t Khi[2][64 * KS_STR];
    __shared__ uint32_t Vhi[2][64 * VS_STR];

    const int t    = threadIdx.x;
    const int w    = t >> 5;
    const int lane = t & 31;
    const int g    = lane >> 2;
    const int tq   = lane & 3;
    const int h    = blockIdx.y;
    const int q0   = blockIdx.x * 128;
    const float sc = 1.44269504088896f / sqrtf((float)DH);

    // ---- stage Q tile (128 x 32) raw into buffer-0 regions ----
    for (int i = t; i < 128 * 8; i += 256) {
        int row = i >> 3, c = (i & 7) << 2;
        float4 qv = *(const float4*)&Qm[(size_t)(q0 + row) * HDIM + h * DH + c];
        uint32_t* dst = (row < 64) ? &Khi[0][row * KS_STR + c]
                                   : &Vhi[0][(row - 64) * VS_STR + c];
        *(float4*)dst = qv;
    }
    __syncthreads();

    // ---- Q fragments (rna hi/lo), scaled; registers for whole kernel ----
    uint32_t qhi[4][4], qlo[4][4];
    {
        int r0 = w * 16 + g;
        int r1 = r0 + 8;
        const float* p0 = (const float*)((r0 < 64) ? &Khi[0][r0 * KS_STR]
                                                   : &Vhi[0][(r0 - 64) * VS_STR]);
        const float* p1 = (const float*)((r1 < 64) ? &Khi[0][r1 * KS_STR]
                                                   : &Vhi[0][(r1 - 64) * VS_STR]);
        #pragma unroll
        for (int kc = 0; kc < 4; kc++) {
            int c0 = kc * 8 + tq, c1 = c0 + 4;
            tfsplit(p0[c0] * sc, qhi[kc][0], qlo[kc][0]);
            tfsplit(p1[c0] * sc, qhi[kc][1], qlo[kc][1]);
            tfsplit(p0[c1] * sc, qhi[kc][2], qlo[kc][2]);
            tfsplit(p1[c1] * sc, qhi[kc][3], qlo[kc][3]);
        }
    }
    __syncthreads();   // all warps done reading Q staging before tile-0 load

    // ---- prefetch tile 0 into buffer 0 (raw fp32, pure copy) ----
    for (int i = t; i < 64 * 8; i += 256) {
        int n = i >> 3, c = (i & 7) << 2;
        size_t gidx = (size_t)n * HDIM + h * DH + c;
        cpa16(&Khi[0][n * KS_STR + c], &Km[gidx]);
        cpa16(&Vhi[0][n * VS_STR + c], &Vm[gidx]);
    }
    asm volatile("cp.async.commit_group;" ::: "memory");

    float oacc[4][4];
    #pragma unroll
    for (int i = 0; i < 4; i++)
        #pragma unroll
        for (int j = 0; j < 4; j++) oacc[i][j] = 0.f;
    float mi[2] = {-1e30f, -1e30f};
    float li[2] = {0.f, 0.f};

    const int ntiles = N >> 6;
    for (int it = 0; it < ntiles; it++) {
        const int p = it & 1;

        // prefetch next tile into the other buffer
        if (it + 1 < ntiles) {
            int kb1 = (it + 1) << 6;
            for (int i = t; i < 64 * 8; i += 256) {
                int n = i >> 3, c = (i & 7) << 2;
                size_t gidx = (size_t)(kb1 + n) * HDIM + h * DH + c;
                cpa16(&Khi[1 - p][n * KS_STR + c], &Km[gidx]);
                cpa16(&Vhi[1 - p][n * VS_STR + c], &Vm[gidx]);
            }
            asm volatile("cp.async.commit_group;" ::: "memory");
            asm volatile("cp.async.wait_group 1;" ::: "memory");
        } else {
            asm volatile("cp.async.wait_group 0;" ::: "memory");
        }

        // rna-round this thread's own copied words in place (same index
        // partition as the issuing loop -> own-data visibility, no barrier)
        for (int i = t; i < 64 * 8; i += 256) {
            int n = i >> 3, c = (i & 7) << 2;
            uint4* kp = (uint4*)&Khi[p][n * KS_STR + c];
            uint4 kw = *kp;
            kw.x = f2tf(__uint_as_float(kw.x));
            kw.y = f2tf(__uint_as_float(kw.y));
            kw.z = f2tf(__uint_as_float(kw.z));
            kw.w = f2tf(__uint_as_float(kw.w));
            *kp = kw;
            uint4* vp = (uint4*)&Vhi[p][n * VS_STR + c];
            uint4 vw = *vp;
            vw.x = f2tf(__uint_as_float(vw.x));
            vw.y = f2tf(__uint_as_float(vw.y));
            vw.z = f2tf(__uint_as_float(vw.z));
            vw.w = f2tf(__uint_as_float(vw.w));
            *vp = vw;
        }
        __syncthreads();   // tile `it` (rounded) visible to all warps

        // ---- S = Q @ K^T : 2xTF32 ----
        float sb[8][4];
        #pragma unroll
        for (int nb = 0; nb < 8; nb++)
            #pragma unroll
            for (int j = 0; j < 4; j++) sb[nb][j] = 0.f;

        #pragma unroll
        for (int kc = 0; kc < 4; kc++) {
            #pragma unroll
            for (int nb = 0; nb < 8; nb++) {
                int base = (nb * 8 + g) * KS_STR + kc * 8 + tq;
                uint32_t b0h = Khi[p][base], b1h = Khi[p][base + 4];
                mma_tf32(sb[nb], qhi[kc], b0h, b1h);
                mma_tf32(sb[nb], qlo[kc], b0h, b1h);
            }
        }

        // ---- online softmax on C fragments ----
        #pragma unroll
        for (int hf = 0; hf < 2; hf++) {
            int e0 = hf * 2, e1 = hf * 2 + 1;
            float rm = -1e30f;
            #pragma unroll
            for (int nb = 0; nb < 8; nb++)
                rm = fmaxf(rm, fmaxf(sb[nb][e0], sb[nb][e1]));
            rm = fmaxf(rm, __shfl_xor_sync(0xffffffffu, rm, 1));
            rm = fmaxf(rm, __shfl_xor_sync(0xffffffffu, rm, 2));
            float mn = fmaxf(mi[hf], rm);
            float c  = exp2f(mi[hf] - mn);
            float rs = 0.f;
            #pragma unroll
            for (int nb = 0; nb < 8; nb++) {
                sb[nb][e0] = exp2f(sb[nb][e0] - mn);
                sb[nb][e1] = exp2f(sb[nb][e1] - mn);
                rs += sb[nb][e0] + sb[nb][e1];
            }
            rs += __shfl_xor_sync(0xffffffffu, rs, 1);
            rs += __shfl_xor_sync(0xffffffffu, rs, 2);
            li[hf] = li[hf] * c + rs;
            mi[hf] = mn;
            #pragma unroll
            for (int nbo = 0; nbo < 4; nbo++) {
                oacc[nbo][e0] *= c;
                oacc[nbo][e1] *= c;
            }
        }

        // ---- O += P @ V : P single rna tf32 in regs, V rna tf32 (1 mma) ----
        const int srcA = (lane & ~3) + (tq >> 1);
        const int srcB = srcA + 2;
        const bool odd = (tq & 1);
        #pragma unroll
        for (int kc = 0; kc < 8; kc++) {
            float vA0 = __shfl_sync(0xffffffffu, sb[kc][0], srcA);
            float vA1 = __shfl_sync(0xffffffffu, sb[kc][1], srcA);
            float vA2 = __shfl_sync(0xffffffffu, sb[kc][2], srcA);
            float vA3 = __shfl_sync(0xffffffffu, sb[kc][3], srcA);
            float vB0 = __shfl_sync(0xffffffffu, sb[kc][0], srcB);
            float vB1 = __shfl_sync(0xffffffffu, sb[kc][1], srcB);
            float vB2 = __shfl_sync(0xffffffffu, sb[kc][2], srcB);
            float vB3 = __shfl_sync(0xffffffffu, sb[kc][3], srcB);
            float pa0 = odd ? vA1 : vA0;
            float pa1 = odd ? vA3 : vA2;
            float pa2 = odd ? vB1 : vB0;
            float pa3 = odd ? vB3 : vB2;
            uint32_t phi[4];
            phi[0] = f2tf(pa0);
            phi[1] = f2tf(pa1);
            phi[2] = f2tf(pa2);
            phi[3] = f2tf(pa3);
            int b0 = (kc * 8 + tq) * VS_STR + g;
            int b1 = (kc * 8 + tq + 4) * VS_STR + g;
            #pragma unroll
            for (int nbo = 0; nbo < 4; nbo++) {
                uint32_t v0h = Vhi[p][b0 + nbo * 8], v1h = Vhi[p][b1 + nbo * 8];
                mma_tf32(oacc[nbo], phi, v0h, v1h);
            }
        }
        __syncthreads();   // tile `it` fully consumed; next prefetch may write
    }

    float inv0 = 1.f / li[0];
    float inv1 = 1.f / li[1];
    int r0 = q0 + w * 16 + g;
    #pragma unroll
    for (int nbo = 0; nbo < 4; nbo++) {
        int col = h * DH + nbo * 8 + tq * 2;
        *(float2*)&O[(size_t)r0 * HDIM + col] =
            make_float2(oacc[nbo][0] * inv0, oacc[nbo][1] * inv0);
        *(float2*)&O[(size_t)(r0 + 8) * HDIM + col] =
            make_float2(oacc[nbo][2] * inv1, oacc[nbo][3] * inv1);
    }
}

// ---------------- edge kernel: Hsum[dst] += relu(Atop[src] + Abot[dst]) ----
__global__ void edge_k(const float* __restrict__ At, const float* __restrict__ Ab,
                       const int* __restrict__ edges, float* __restrict__ Hsum,
                       float* __restrict__ deg, int E)
{
    const int lane   = threadIdx.x & 31;
    const int gw     = (blockIdx.x * blockDim.x + threadIdx.x) >> 5;
    const int nwarps = (gridDim.x * blockDim.x) >> 5;

    for (int e = gw; e < E; e += nwarps) {
        int src = edges[2 * e + 0];
        int dst = edges[2 * e + 1];
        const float4* ps = (const float4*)(At + (size_t)src * HDIM);
        const float4* pd = (const float4*)(Ab + (size_t)dst * HDIM);
        float* po = Hsum + (size_t)dst * HDIM;
        #pragma unroll
        for (int i = 0; i < 2; i++) {
            int idx = lane + 32 * i;
            float4 a = ps[idx], b = pd[idx];
            float4 r;
            r.x = fmaxf(a.x + b.x, 0.f);
            r.y = fmaxf(a.y + b.y, 0.f);
            r.z = fmaxf(a.z + b.z, 0.f);
            r.w = fmaxf(a.w + b.w, 0.f);
            asm volatile("red.global.add.v4.f32 [%0], {%1, %2, %3, %4};"
                         :: "l"(po + idx * 4), "f"(r.x), "f"(r.y), "f"(r.z), "f"(r.w)
                         : "memory");
        }
        if (lane == 0) atomicAdd(deg + dst, 1.f);
    }
}

// ---------------- launch ---------------------------------------------------
extern "C" void kernel_launch(void* const* d_in, const int* in_sizes, int n_in,
                              void* d_out, int out_size)
{
    const float* x    = (const float*)d_in[0];
    const int*   edges= (const int*)  d_in[1];
    const float* Wq   = (const float*)d_in[2];
    const float* Wk   = (const float*)d_in[3];
    const float* Wv   = (const float*)d_in[4];
    const float* bq   = (const float*)d_in[5];
    const float* bk   = (const float*)d_in[6];
    const float* bv   = (const float*)d_in[7];
    const float* Wo   = (const float*)d_in[8];
    const float* bo   = (const float*)d_in[9];
    const float* Wm1  = (const float*)d_in[10];
    const float* bm1  = (const float*)d_in[11];
    const float* Wm2  = (const float*)d_in[12];
    const float* bm2  = (const float*)d_in[13];
    const float* Wu1  = (const float*)d_in[14];
    const float* bu1  = (const float*)d_in[15];
    const float* Wu2  = (const float*)d_in[16];
    const float* bu2  = (const float*)d_in[17];
    float* out = (float*)d_out;

    const int N = in_sizes[0] / HDIM;   // 4096
    const int E = in_sizes[1] / 2;      // 131072

    float *Q, *K, *V, *attH, *att, *Atop, *Abot, *Hsum, *msg, *T1, *deg;
    cudaGetSymbolAddress((void**)&Q,    g_Q);
    cudaGetSymbolAddress((void**)&K,    g_K);
    cudaGetSymbolAddress((void**)&V,    g_V);
    cudaGetSymbolAddress((void**)&attH, g_attH);
    cudaGetSymbolAddress((void**)&att,  g_att);
    cudaGetSymbolAddress((void**)&Atop, g_Atop);
    cudaGetSymbolAddress((void**)&Abot, g_Abot);
    cudaGetSymbolAddress((void**)&Hsum, g_Hsum);
    cudaGetSymbolAddress((void**)&msg,  g_msg);
    cudaGetSymbolAddress((void**)&T1,   g_T1);
    cudaGetSymbolAddress((void**)&deg,  g_deg);

    dim3 gB(256);
    dim3 gG (HDIM / 64, N / 64);        // (4, 64)  = 256 blocks
    dim3 gG3(HDIM / 64, N / 64, 3);     // (4, 64, 3) = 768 blocks

    cudaMemsetAsync(Hsum, 0, (size_t)N * HDIM * sizeof(float));
    cudaMemsetAsync(deg,  0, (size_t)N * sizeof(float));

    // QKV projections (batched: blockIdx.z selects q/k/v)
    Jobs3 jq;
    jq.W[0] = Wq; jq.W[1] = Wk; jq.W[2] = Wv;
    jq.bias[0] = bq; jq.bias[1] = bk; jq.bias[2] = bv;
    jq.C[0] = Q; jq.C[1] = K; jq.C[2] = V;
    gemm_mma3<<<gG3, gB>>>(x, jq, N, HDIM, HDIM);

    // attention (tensor cores, cp.async double-buffered, asymmetric tf32)
    flash_mma<<<dim3(N / 128, NHEADS), 256>>>(Q, K, V, attH, N);

    // output projection
    gemm_mma<false, false, false><<<gG, gB>>>(attH, Wo, bo, nullptr, nullptr, att, N, HDIM, HDIM);

    // batched: Atop = att@Wm1[:256]+bm1 ; Abot = att@Wm1[256:] ; T1 = att@Wu1[:256]+bu1
    Jobs3 ja;
    ja.W[0] = Wm1; ja.W[1] = Wm1 + HDIM * HDIM; ja.W[2] = Wu1;
    ja.bias[0] = bm1; ja.bias[1] = nullptr; ja.bias[2] = bu1;
    ja.C[0] = Atop; ja.C[1] = Abot; ja.C[2] = T1;
    gemm_mma3<<<gG3, gB>>>(att, ja, N, HDIM, HDIM);

    // per-edge relu + segment-sum of hidden
    edge_k<<<512, 256>>>(Atop, Abot, edges, Hsum, deg, E);

    // messages = Hsum @ Wm2 + deg * bm2
    gemm_mma<false, false, true><<<gG, gB>>>(Hsum, Wm2, bm2, nullptr, deg, msg, N, HDIM, HDIM);

    // T1 = relu(msg @ Wu1[256:] + T1)
    gemm_mma<true, true, false><<<gG, gB>>>(msg, Wu1 + HDIM * HDIM, nullptr, T1, nullptr, T1, N, HDIM, HDIM);

    // output
    gemm_mma<false, false, false><<<gG, gB>>>(T1, Wu2, bu2, nullptr, nullptr, out, N, HDIM, HDIM);
}

// round 16
// speedup vs baseline: 1.2205x; 1.0780x over previous
#include <cuda_runtime.h>
#include <math.h>
#include <stdint.h>

#define HDIM 256
#define NHEADS 8
#define DH 32
#define NMAX 4096

// ---------------- scratch (static __device__ arrays: no allocations) -------
__device__ __align__(16) float g_Q   [NMAX * HDIM];
__device__ __align__(16) float g_K   [NMAX * HDIM];
__device__ __align__(16) float g_V   [NMAX * HDIM];
__device__ __align__(16) float g_attH[NMAX * HDIM];
__device__ __align__(16) float g_att [NMAX * HDIM];
__device__ __align__(16) float g_Atop[NMAX * HDIM];
__device__ __align__(16) float g_Abot[NMAX * HDIM];
__device__ __align__(16) float g_Hsum[NMAX * HDIM];
__device__ __align__(16) float g_msg [NMAX * HDIM];
__device__ __align__(16) float g_T1  [NMAX * HDIM];
__device__ __align__(16) float g_deg [NMAX];

// ---------------- tf32 helpers ---------------------------------------------
__device__ __forceinline__ uint32_t f2tf(float x) {
    uint32_t r;
    asm("cvt.rna.tf32.f32 %0, %1;" : "=r"(r) : "f"(x));
    return r;
}
__device__ __forceinline__ void tfsplit(float x, uint32_t& hi, uint32_t& lo) {
    hi = f2tf(x);
    lo = f2tf(x - __uint_as_float(hi));
}
__device__ __forceinline__ void mma_tf32(float d[4], const uint32_t a[4],
                                         uint32_t b0, uint32_t b1) {
    asm volatile(
        "mma.sync.aligned.m16n8k8.row.col.f32.tf32.tf32.f32 "
        "{%0,%1,%2,%3}, {%4,%5,%6,%7}, {%8,%9}, {%0,%1,%2,%3};"
        : "+f"(d[0]), "+f"(d[1]), "+f"(d[2]), "+f"(d[3])
        : "r"(a[0]), "r"(a[1]), "r"(a[2]), "r"(a[3]), "r"(b0), "r"(b1));
}
__device__ __forceinline__ void cpa16(void* smem, const void* g) {
    uint32_t s = (uint32_t)__cvta_generic_to_shared(smem);
    asm volatile("cp.async.cg.shared.global [%0], [%1], 16;"
                 :: "r"(s), "l"(g) : "memory");
}

struct Jobs3 {
    const float* W[3];
    const float* bias[3];
    float*       C[3];
};

// ---------------- tensor-core GEMM body (2xTF32, A truncated) ---------------
// A is a SINGLE rna tf32 (activations); W keeps the hi/lo split. Per logical
// mma: 2 HW mmas (ah.bh + ah.bl). Neglected A_lo.W term is unbiased ~1.2e-4
// relative per GEMM — validated by the flash 2x path (measured 9.8e-5).
// Removing Alo cuts inner-loop LDS -33% (the L1-bound resource), mma -33%,
// and the A-loader tfsplit becomes a bare cvt.
#define AS_STR 36
#define WS_STR 72

template<bool RELU, bool ADD, bool DEGB>
__device__ __forceinline__ void gemm_body(
    const float* __restrict__ A, const float* __restrict__ W,
    const float* bias, const float* __restrict__ Dadd,
    const float* __restrict__ deg, float* __restrict__ C,
    int M, int K, int N,
    uint32_t* Ahi, uint32_t* Whi, uint32_t* Wlo)
{
    const int t    = threadIdx.x;
    const int w    = t >> 5;
    const int lane = t & 31;
    const int g    = lane >> 2;
    const int tq   = lane & 3;
    const int wm   = (w >> 2) * 32;
    const int wn   = (w & 3) * 16;
    const int bm   = blockIdx.y * 64;
    const int bn   = blockIdx.x * 64;

    float acc[2][2][4];
    #pragma unroll
    for (int mh = 0; mh < 2; mh++)
        #pragma unroll
        for (int nb = 0; nb < 2; nb++)
            #pragma unroll
            for (int j = 0; j < 4; j++) acc[mh][nb][j] = 0.f;

    const int arow = t >> 2, akb = (t & 3) * 8;
    const int wkk  = t >> 3, wnb = (t & 7) * 8;

    for (int k0 = 0; k0 < K; k0 += 32) {
        __syncthreads();
        {
            const float* src = &A[(size_t)(bm + arow) * K + k0 + akb];
            #pragma unroll
            for (int j = 0; j < 8; j += 4) {
                float4 v = *(const float4*)(src + j);
                *(uint4*)&Ahi[arow * AS_STR + akb + j] =
                    make_uint4(f2tf(v.x), f2tf(v.y), f2tf(v.z), f2tf(v.w));
            }
        }
        {
            const float* src = &W[(size_t)(k0 + wkk) * N + bn + wnb];
            #pragma unroll
            for (int j = 0; j < 8; j += 4) {
                float4 v = *(const float4*)(src + j);
                uint32_t h0,l0,h1,l1,h2,l2,h3,l3;
                tfsplit(v.x,h0,l0); tfsplit(v.y,h1,l1);
                tfsplit(v.z,h2,l2); tfsplit(v.w,h3,l3);
                *(uint4*)&Whi[wkk * WS_STR + wnb + j] = make_uint4(h0,h1,h2,h3);
                *(uint4*)&Wlo[wkk * WS_STR + wnb + j] = make_uint4(l0,l1,l2,l3);
            }
        }
        __syncthreads();

        #pragma unroll
        for (int kc = 0; kc < 4; kc++) {
            uint32_t bh[2][2], bl[2][2];
            #pragma unroll
            for (int nb = 0; nb < 2; nb++) {
                int i0 = (kc * 8 + tq) * WS_STR + wn + nb * 8 + g;
                int i1 = i0 + 4 * WS_STR;
                bh[nb][0] = Whi[i0]; bh[nb][1] = Whi[i1];
                bl[nb][0] = Wlo[i0]; bl[nb][1] = Wlo[i1];
            }
            #pragma unroll
            for (int mh = 0; mh < 2; mh++) {
                int r0 = (wm + mh * 16 + g) * AS_STR + kc * 8 + tq;
                int r1 = r0 + 8 * AS_STR;
                uint32_t ah[4] = {Ahi[r0], Ahi[r1], Ahi[r0 + 4], Ahi[r1 + 4]};
                #pragma unroll
                for (int nb = 0; nb < 2; nb++) {
                    mma_tf32(acc[mh][nb], ah, bh[nb][0], bh[nb][1]);
                    mma_tf32(acc[mh][nb], ah, bl[nb][0], bl[nb][1]);
                }
            }
        }
    }

    #pragma unroll
    for (int mh = 0; mh < 2; mh++) {
        int row0 = bm + wm + mh * 16 + g;
        int row1 = row0 + 8;
        float d0 = DEGB ? deg[row0] : 1.f;
        float d1 = DEGB ? deg[row1] : 1.f;
        #pragma unroll
        for (int nb = 0; nb < 2; nb++) {
            int col = bn + wn + nb * 8 + tq * 2;
            float v0 = acc[mh][nb][0], v1 = acc[mh][nb][1];
            float v2 = acc[mh][nb][2], v3 = acc[mh][nb][3];
            if (ADD) {
                float2 x0 = *(const float2*)&Dadd[(size_t)row0 * N + col];
                float2 x1 = *(const float2*)&Dadd[(size_t)row1 * N + col];
                v0 += x0.x; v1 += x0.y; v2 += x1.x; v3 += x1.y;
            }
            if (bias) {
                float b0 = bias[col], b1 = bias[col + 1];
                if (DEGB) { v0 += d0 * b0; v1 += d0 * b1; v2 += d1 * b0; v3 += d1 * b1; }
                else      { v0 += b0;      v1 += b1;      v2 += b0;      v3 += b1; }
            }
            if (RELU) {
                v0 = fmaxf(v0, 0.f); v1 = fmaxf(v1, 0.f);
                v2 = fmaxf(v2, 0.f); v3 = fmaxf(v3, 0.f);
            }
            *(float2*)&C[(size_t)row0 * N + col] = make_float2(v0, v1);
            *(float2*)&C[(size_t)row1 * N + col] = make_float2(v2, v3);
        }
    }
}

template<bool RELU, bool ADD, bool DEGB>
__global__ void __launch_bounds__(256) gemm_mma(
    const float* __restrict__ A, const float* __restrict__ W,
    const float* bias, const float* __restrict__ Dadd,
    const float* __restrict__ deg, float* __restrict__ C,
    int M, int K, int N)
{
    __shared__ uint32_t Ahi[64 * AS_STR];
    __shared__ uint32_t Whi[32 * WS_STR];
    __shared__ uint32_t Wlo[32 * WS_STR];
    gemm_body<RELU, ADD, DEGB>(A, W, bias, Dadd, deg, C, M, K, N,
                               Ahi, Whi, Wlo);
}

// batched variant: blockIdx.z selects (W, bias, C); same A for all three.
__global__ void __launch_bounds__(256) gemm_mma3(
    const float* __restrict__ A, Jobs3 jobs, int M, int K, int N)
{
    __shared__ uint32_t Ahi[64 * AS_STR];
    __shared__ uint32_t Whi[32 * WS_STR];
    __shared__ uint32_t Wlo[32 * WS_STR];
    const int z = blockIdx.z;
    gemm_body<false, false, false>(A, jobs.W[z], jobs.bias[z], nullptr, nullptr,
                                   jobs.C[z], M, K, N, Ahi, Whi, Wlo);
}

// ---------------- flash attention: cp.async double-buffer, asymmetric tf32 --
// (unchanged from round 15 — passing at 410.6us total, rel_err 1.15e-4)
#define KS_STR 36
#define VS_STR 40

__global__ void __launch_bounds__(256) flash_mma(
    const float* __restrict__ Qm, const float* __restrict__ Km,
    const float* __restrict__ Vm, float* __restrict__ O, int N)
{
    __shared__ uint32_t Khi[2][64 * KS_STR];
    __shared__ uint32_t Vhi[2][64 * VS_STR];

    const int t    = threadIdx.x;
    const int w    = t >> 5;
    const int lane = t & 31;
    const int g    = lane >> 2;
    const int tq   = lane & 3;
    const int h    = blockIdx.y;
    const int q0   = blockIdx.x * 128;
    const float sc = 1.44269504088896f / sqrtf((float)DH);

    // ---- stage Q tile (128 x 32) raw into buffer-0 regions ----
    for (int i = t; i < 128 * 8; i += 256) {
        int row = i >> 3, c = (i & 7) << 2;
        float4 qv = *(const float4*)&Qm[(size_t)(q0 + row) * HDIM + h * DH + c];
        uint32_t* dst = (row < 64) ? &Khi[0][row * KS_STR + c]
                                   : &Vhi[0][(row - 64) * VS_STR + c];
        *(float4*)dst = qv;
    }
    __syncthreads();

    // ---- Q fragments (rna hi/lo), scaled; registers for whole kernel ----
    uint32_t qhi[4][4], qlo[4][4];
    {
        int r0 = w * 16 + g;
        int r1 = r0 + 8;
        const float* p0 = (const float*)((r0 < 64) ? &Khi[0][r0 * KS_STR]
                                                   : &Vhi[0][(r0 - 64) * VS_STR]);
        const float* p1 = (const float*)((r1 < 64) ? &Khi[0][r1 * KS_STR]
                                                   : &Vhi[0][(r1 - 64) * VS_STR]);
        #pragma unroll
        for (int kc = 0; kc < 4; kc++) {
            int c0 = kc * 8 + tq, c1 = c0 + 4;
            tfsplit(p0[c0] * sc, qhi[kc][0], qlo[kc][0]);
            tfsplit(p1[c0] * sc, qhi[kc][1], qlo[kc][1]);
            tfsplit(p0[c1] * sc, qhi[kc][2], qlo[kc][2]);
            tfsplit(p1[c1] * sc, qhi[kc][3], qlo[kc][3]);
        }
    }
    __syncthreads();   // all warps done reading Q staging before tile-0 load

    // ---- prefetch tile 0 into buffer 0 (raw fp32, pure copy) ----
    for (int i = t; i < 64 * 8; i += 256) {
        int n = i >> 3, c = (i & 7) << 2;
        size_t gidx = (size_t)n * HDIM + h * DH + c;
        cpa16(&Khi[0][n * KS_STR + c], &Km[gidx]);
        cpa16(&Vhi[0][n * VS_STR + c], &Vm[gidx]);
    }
    asm volatile("cp.async.commit_group;" ::: "memory");

    float oacc[4][4];
    #pragma unroll
    for (int i = 0; i < 4; i++)
        #pragma unroll
        for (int j = 0; j < 4; j++) oacc[i][j] = 0.f;
    float mi[2] = {-1e30f, -1e30f};
    float li[2] = {0.f, 0.f};

    const int ntiles = N >> 6;
    for (int it = 0; it < ntiles; it++) {
        const int p = it & 1;

        // prefetch next tile into the other buffer
        if (it + 1 < ntiles) {
            int kb1 = (it + 1) << 6;
            for (int i = t; i < 64 * 8; i += 256) {
                int n = i >> 3, c = (i & 7) << 2;
                size_t gidx = (size_t)(kb1 + n) * HDIM + h * DH + c;
                cpa16(&Khi[1 - p][n * KS_STR + c], &Km[gidx]);
                cpa16(&Vhi[1 - p][n * VS_STR + c], &Vm[gidx]);
            }
            asm volatile("cp.async.commit_group;" ::: "memory");
            asm volatile("cp.async.wait_group 1;" ::: "memory");
        } else {
            asm volatile("cp.async.wait_group 0;" ::: "memory");
        }

        // rna-round this thread's own copied words in place (same index
        // partition as the issuing loop -> own-data visibility, no barrier)
        for (int i = t; i < 64 * 8; i += 256) {
            int n = i >> 3, c = (i & 7) << 2;
            uint4* kp = (uint4*)&Khi[p][n * KS_STR + c];
            uint4 kw = *kp;
            kw.x = f2tf(__uint_as_float(kw.x));
            kw.y = f2tf(__uint_as_float(kw.y));
            kw.z = f2tf(__uint_as_float(kw.z));
            kw.w = f2tf(__uint_as_float(kw.w));
            *kp = kw;
            uint4* vp = (uint4*)&Vhi[p][n * VS_STR + c];
            uint4 vw = *vp;
            vw.x = f2tf(__uint_as_float(vw.x));
            vw.y = f2tf(__uint_as_float(vw.y));
            vw.z = f2tf(__uint_as_float(vw.z));
            vw.w = f2tf(__uint_as_float(vw.w));
            *vp = vw;
        }
        __syncthreads();   // tile `it` (rounded) visible to all warps

        // ---- S = Q @ K^T : 2xTF32 ----
        float sb[8][4];
        #pragma unroll
        for (int nb = 0; nb < 8; nb++)
            #pragma unroll
            for (int j = 0; j < 4; j++) sb[nb][j] = 0.f;

        #pragma unroll
        for (int kc = 0; kc < 4; kc++) {
            #pragma unroll
            for (int nb = 0; nb < 8; nb++) {
                int base = (nb * 8 + g) * KS_STR + kc * 8 + tq;
                uint32_t b0h = Khi[p][base], b1h = Khi[p][base + 4];
                mma_tf32(sb[nb], qhi[kc], b0h, b1h);
                mma_tf32(sb[nb], qlo[kc], b0h, b1h);
            }
        }

        // ---- online softmax on C fragments ----
        #pragma unroll
        for (int hf = 0; hf < 2; hf++) {
            int e0 = hf * 2, e1 = hf * 2 + 1;
            float rm = -1e30f;
            #pragma unroll
            for (int nb = 0; nb < 8; nb++)
                rm = fmaxf(rm, fmaxf(sb[nb][e0], sb[nb][e1]));
            rm = fmaxf(rm, __shfl_xor_sync(0xffffffffu, rm, 1));
            rm = fmaxf(rm, __shfl_xor_sync(0xffffffffu, rm, 2));
            float mn = fmaxf(mi[hf], rm);
            float c  = exp2f(mi[hf] - mn);
            float rs = 0.f;
            #pragma unroll
            for (int nb = 0; nb < 8; nb++) {
                sb[nb][e0] = exp2f(sb[nb][e0] - mn);
                sb[nb][e1] = exp2f(sb[nb][e1] - mn);
                rs += sb[nb][e0] + sb[nb][e1];
            }
            rs += __shfl_xor_sync(0xffffffffu, rs, 1);
            rs += __shfl_xor_sync(0xffffffffu, rs, 2);
            li[hf] = li[hf] * c + rs;
            mi[hf] = mn;
            #pragma unroll
            for (int nbo = 0; nbo < 4; nbo++) {
                oacc[nbo][e0] *= c;
                oacc[nbo][e1] *= c;
            }
        }

        // ---- O += P @ V : P single rna tf32 in regs, V rna tf32 (1 mma) ----
        const int srcA = (lane & ~3) + (tq >> 1);
        const int srcB = srcA + 2;
        const bool odd = (tq & 1);
        #pragma unroll
        for (int kc = 0; kc < 8; kc++) {
            float vA0 = __shfl_sync(0xffffffffu, sb[kc][0], srcA);
            float vA1 = __shfl_sync(0xffffffffu, sb[kc][1], srcA);
            float vA2 = __shfl_sync(0xffffffffu, sb[kc][2], srcA);
            float vA3 = __shfl_sync(0xffffffffu, sb[kc][3], srcA);
            float vB0 = __shfl_sync(0xffffffffu, sb[kc][0], srcB);
            float vB1 = __shfl_sync(0xffffffffu, sb[kc][1], srcB);
            float vB2 = __shfl_sync(0xffffffffu, sb[kc][2], srcB);
            float vB3 = __shfl_sync(0xffffffffu, sb[kc][3], srcB);
            float pa0 = odd ? vA1 : vA0;
            float pa1 = odd ? vA3 : vA2;
            float pa2 = odd ? vB1 : vB0;
            float pa3 = odd ? vB3 : vB2;
            uint32_t phi[4];
            phi[0] = f2tf(pa0);
            phi[1] = f2tf(pa1);
            phi[2] = f2tf(pa2);
            phi[3] = f2tf(pa3);
            int b0 = (kc * 8 + tq) * VS_STR + g;
            int b1 = (kc * 8 + tq + 4) * VS_STR + g;
            #pragma unroll
            for (int nbo = 0; nbo < 4; nbo++) {
                uint32_t v0h = Vhi[p][b0 + nbo * 8], v1h = Vhi[p][b1 + nbo * 8];
                mma_tf32(oacc[nbo], phi, v0h, v1h);
            }
        }
        __syncthreads();   // tile `it` fully consumed; next prefetch may write
    }

    float inv0 = 1.f / li[0];
    float inv1 = 1.f / li[1];
    int r0 = q0 + w * 16 + g;
    #pragma unroll
    for (int nbo = 0; nbo < 4; nbo++) {
        int col = h * DH + nbo * 8 + tq * 2;
        *(float2*)&O[(size_t)r0 * HDIM + col] =
            make_float2(oacc[nbo][0] * inv0, oacc[nbo][1] * inv0);
        *(float2*)&O[(size_t)(r0 + 8) * HDIM + col] =
            make_float2(oacc[nbo][2] * inv1, oacc[nbo][3] * inv1);
    }
}

// ---------------- edge kernel: Hsum[dst] += relu(Atop[src] + Abot[dst]) ----
__global__ void edge_k(const float* __restrict__ At, const float* __restrict__ Ab,
                       const int* __restrict__ edges, float* __restrict__ Hsum,
                       float* __restrict__ deg, int E)
{
    const int lane   = threadIdx.x & 31;
    const int gw     = (blockIdx.x * blockDim.x + threadIdx.x) >> 5;
    const int nwarps = (gridDim.x * blockDim.x) >> 5;

    for (int e = gw; e < E; e += nwarps) {
        int src = edges[2 * e + 0];
        int dst = edges[2 * e + 1];
        const float4* ps = (const float4*)(At + (size_t)src * HDIM);
        const float4* pd = (const float4*)(Ab + (size_t)dst * HDIM);
        float* po = Hsum + (size_t)dst * HDIM;
        #pragma unroll
        for (int i = 0; i < 2; i++) {
            int idx = lane + 32 * i;
            float4 a = ps[idx], b = pd[idx];
            float4 r;
            r.x = fmaxf(a.x + b.x, 0.f);
            r.y = fmaxf(a.y + b.y, 0.f);
            r.z = fmaxf(a.z + b.z, 0.f);
            r.w = fmaxf(a.w + b.w, 0.f);
            asm volatile("red.global.add.v4.f32 [%0], {%1, %2, %3, %4};"
                         :: "l"(po + idx * 4), "f"(r.x), "f"(r.y), "f"(r.z), "f"(r.w)
                         : "memory");
        }
        if (lane == 0) atomicAdd(deg + dst, 1.f);
    }
}

// ---------------- launch ---------------------------------------------------
extern "C" void kernel_launch(void* const* d_in, const int* in_sizes, int n_in,
                              void* d_out, int out_size)
{
    const float* x    = (const float*)d_in[0];
    const int*   edges= (const int*)  d_in[1];
    const float* Wq   = (const float*)d_in[2];
    const float* Wk   = (const float*)d_in[3];
    const float* Wv   = (const float*)d_in[4];
    const float* bq   = (const float*)d_in[5];
    const float* bk   = (const float*)d_in[6];
    const float* bv   = (const float*)d_in[7];
    const float* Wo   = (const float*)d_in[8];
    const float* bo   = (const float*)d_in[9];
    const float* Wm1  = (const float*)d_in[10];
    const float* bm1  = (const float*)d_in[11];
    const float* Wm2  = (const float*)d_in[12];
    const float* bm2  = (const float*)d_in[13];
    const float* Wu1  = (const float*)d_in[14];
    const float* bu1  = (const float*)d_in[15];
    const float* Wu2  = (const float*)d_in[16];
    const float* bu2  = (const float*)d_in[17];
    float* out = (float*)d_out;

    const int N = in_sizes[0] / HDIM;   // 4096
    const int E = in_sizes[1] / 2;      // 131072

    float *Q, *K, *V, *attH, *att, *Atop, *Abot, *Hsum, *msg, *T1, *deg;
    cudaGetSymbolAddress((void**)&Q,    g_Q);
    cudaGetSymbolAddress((void**)&K,    g_K);
    cudaGetSymbolAddress((void**)&V,    g_V);
    cudaGetSymbolAddress((void**)&attH, g_attH);
    cudaGetSymbolAddress((void**)&att,  g_att);
    cudaGetSymbolAddress((void**)&Atop, g_Atop);
    cudaGetSymbolAddress((void**)&Abot, g_Abot);
    cudaGetSymbolAddress((void**)&Hsum, g_Hsum);
    cudaGetSymbolAddress((void**)&msg,  g_msg);
    cudaGetSymbolAddress((void**)&T1,   g_T1);
    cudaGetSymbolAddress((void**)&deg,  g_deg);

    dim3 gB(256);
    dim3 gG (HDIM / 64, N / 64);        // (4, 64)  = 256 blocks
    dim3 gG3(HDIM / 64, N / 64, 3);     // (4, 64, 3) = 768 blocks

    cudaMemsetAsync(Hsum, 0, (size_t)N * HDIM * sizeof(float));
    cudaMemsetAsync(deg,  0, (size_t)N * sizeof(float));

    // QKV projections (batched: blockIdx.z selects q/k/v)
    Jobs3 jq;
    jq.W[0] = Wq; jq.W[1] = Wk; jq.W[2] = Wv;
    jq.bias[0] = bq; jq.bias[1] = bk; jq.bias[2] = bv;
    jq.C[0] = Q; jq.C[1] = K; jq.C[2] = V;
    gemm_mma3<<<gG3, gB>>>(x, jq, N, HDIM, HDIM);

    // attention (tensor cores, cp.async double-buffered, asymmetric tf32)
    flash_mma<<<dim3(N / 128, NHEADS), 256>>>(Q, K, V, attH, N);

    // output projection
    gemm_mma<false, false, false><<<gG, gB>>>(attH, Wo, bo, nullptr, nullptr, att, N, HDIM, HDIM);

    // batched: Atop = att@Wm1[:256]+bm1 ; Abot = att@Wm1[256:] ; T1 = att@Wu1[:256]+bu1
    Jobs3 ja;
    ja.W[0] = Wm1; ja.W[1] = Wm1 + HDIM * HDIM; ja.W[2] = Wu1;
    ja.bias[0] = bm1; ja.bias[1] = nullptr; ja.bias[2] = bu1;
    ja.C[0] = Atop; ja.C[1] = Abot; ja.C[2] = T1;
    gemm_mma3<<<gG3, gB>>>(att, ja, N, HDIM, HDIM);

    // per-edge relu + segment-sum of hidden
    edge_k<<<512, 256>>>(Atop, Abot, edges, Hsum, deg, E);

    // messages = Hsum @ Wm2 + deg * bm2
    gemm_mma<false, false, true><<<gG, gB>>>(Hsum, Wm2, bm2, nullptr, deg, msg, N, HDIM, HDIM);

    // T1 = relu(msg @ Wu1[256:] + T1)
    gemm_mma<true, true, false><<<gG, gB>>>(msg, Wu1 + HDIM * HDIM, nullptr, T1, nullptr, T1, N, HDIM, HDIM);

    // output
    gemm_mma<false, false, false><<<gG, gB>>>(T1, Wu2, bu2, nullptr, nullptr, out, N, HDIM, HDIM);
}